// round 1
// baseline (speedup 1.0000x reference)
#include <cuda_runtime.h>

#define E_DIM 256
#define D_DIM 128
#define TT    32     // tokens per CTA
#define QP    264    // padded row stride (floats) for q/k/v smem tiles

// Folded weights/biases (P merged into Wq, Wk; Wv transposed). Static device
// globals — no allocation.
__device__ float g_Wq[E_DIM * E_DIM];
__device__ float g_Wk[E_DIM * E_DIM];
__device__ float g_Wv[E_DIM * E_DIM];
__device__ float g_bq[E_DIM];
__device__ float g_bk[E_DIM];
__device__ float g_bv[E_DIM];

// Weff_q[e][j] = sum_d Wq[h*D + d][e] * P[d][j%D],  h = j / D
// so that  q' (post-P) = x @ Weff_q + b'   in one GEMM.
__global__ void prep_kernel(const float* __restrict__ Wq, const float* __restrict__ bq,
                            const float* __restrict__ Wk, const float* __restrict__ bk,
                            const float* __restrict__ Wv, const float* __restrict__ bv,
                            const float* __restrict__ P) {
    int e = blockIdx.x;    // input feature
    int j = threadIdx.x;   // output column
    int h = j >> 7;
    int jm = j & 127;
    float aq = 0.f, ak = 0.f;
#pragma unroll 4
    for (int d = 0; d < D_DIM; ++d) {
        float p = P[d * D_DIM + jm];
        aq = fmaf(Wq[(h * D_DIM + d) * E_DIM + e], p, aq);
        ak = fmaf(Wk[(h * D_DIM + d) * E_DIM + e], p, ak);
    }
    g_Wq[e * E_DIM + j] = aq;
    g_Wk[e * E_DIM + j] = ak;
    g_Wv[e * E_DIM + j] = Wv[j * E_DIM + e];   // nn.Linear: y = x @ W^T
    if (e == 0) {
        float bqe = 0.f, bke = 0.f;
        for (int d = 0; d < D_DIM; ++d) {
            float p = P[d * D_DIM + jm];
            bqe = fmaf(bq[h * D_DIM + d], p, bqe);
            bke = fmaf(bk[h * D_DIM + d], p, bke);
        }
        g_bq[j] = bqe;
        g_bk[j] = bke;
        g_bv[j] = bv[j];
    }
}

// One CTA = 32 tokens. Computes q', k', v tiles in registers (smem-staged
// weights), parks them in smem, then does the 8-token block-diagonal
// attention entirely in-CTA and writes the final output. q/k/v never touch
// global memory.
__global__ __launch_bounds__(256, 1)
void fused_kernel(const float* __restrict__ x, float* __restrict__ out) {
    extern __shared__ float sm[];
    float* xs  = sm;                    // [32][256]  x tile
    float* ws  = xs + TT * E_DIM;       // [32][256]  weight k-chunk
    float* qs  = ws + TT * E_DIM;       // [32][QP]
    float* ks  = qs + TT * QP;          // [32][QP]
    float* vs  = ks + TT * QP;          // [32][QP]
    float* as_ = vs + TT * QP;          // [8][64]    attention probs per warp

    const int tid  = threadIdx.x;
    const int w    = tid >> 5;          // warp 0..7
    const int lane = tid & 31;

    // ---- load x tile (coalesced float4) ----
    {
        const float4* xg = (const float4*)(x + (size_t)blockIdx.x * TT * E_DIM);
        float4* xs4 = (float4*)xs;
#pragma unroll
        for (int i = 0; i < 8; ++i) xs4[tid + 256 * i] = xg[tid + 256 * i];
    }

    const float* Wp[3]  = {g_Wq, g_Wk, g_Wv};
    const float* bpp[3] = {g_bq, g_bk, g_bv};
    float* op[3]        = {qs, ks, vs};

    // ---- three GEMMs: [32,256] x [256,256], register tile 4 rows x 8 cols ----
    // warp w owns rows 4w..4w+3; lane owns cols {lane + 32*cc}
    for (int p = 0; p < 3; ++p) {
        float acc[4][8];
#pragma unroll
        for (int cc = 0; cc < 8; ++cc) {
            float bb = bpp[p][lane + 32 * cc];
#pragma unroll
            for (int r = 0; r < 4; ++r) acc[r][cc] = bb;
        }
        const float* W = Wp[p];
        for (int kk = 0; kk < E_DIM; kk += TT) {
            __syncthreads();
            {
                const float4* wg = (const float4*)(W + kk * E_DIM);
                float4* ws4 = (float4*)ws;
#pragma unroll
                for (int i = 0; i < 8; ++i) ws4[tid + 256 * i] = wg[tid + 256 * i];
            }
            __syncthreads();
#pragma unroll 4
            for (int k = 0; k < TT; ++k) {
                float xv[4], wv[8];
#pragma unroll
                for (int r = 0; r < 4; ++r) xv[r] = xs[(4 * w + r) * E_DIM + kk + k];
#pragma unroll
                for (int cc = 0; cc < 8; ++cc) wv[cc] = ws[k * E_DIM + lane + 32 * cc];
#pragma unroll
                for (int r = 0; r < 4; ++r)
#pragma unroll
                    for (int cc = 0; cc < 8; ++cc)
                        acc[r][cc] = fmaf(xv[r], wv[cc], acc[r][cc]);
            }
        }
        float* o = op[p];
#pragma unroll
        for (int r = 0; r < 4; ++r)
#pragma unroll
            for (int cc = 0; cc < 8; ++cc)
                o[(4 * w + r) * QP + lane + 32 * cc] = acc[r][cc];
    }
    __syncthreads();

    // ---- block-diagonal attention: warp w -> block b = w>>1, head h = w&1 ----
    const int b = w >> 1;
    const int h = w & 1;
    const int i0 = lane >> 3, j0 = lane & 7;   // lane covers (i0,j0) and (i0+4,j0)

    const float4* q0 = (const float4*)(qs + (8 * b + i0) * QP + h * D_DIM);
    const float4* q1 = (const float4*)(qs + (8 * b + i0 + 4) * QP + h * D_DIM);
    const float4* k0 = (const float4*)(ks + (8 * b + j0) * QP + h * D_DIM);

    float s0 = 0.f, s1 = 0.f;
#pragma unroll
    for (int t = 0; t < D_DIM / 4; ++t) {
        float4 kq = k0[t];
        float4 a  = q0[t];
        s0 += a.x * kq.x + a.y * kq.y + a.z * kq.z + a.w * kq.w;
        float4 c  = q1[t];
        s1 += c.x * kq.x + c.y * kq.y + c.z * kq.z + c.w * kq.w;
    }
    const float scl = 0.08838834764831845f;    // 1/sqrt(128)
    s0 *= scl; s1 *= scl;

    // softmax over j within groups of 8 lanes (same i)
    float m0 = s0, m1 = s1;
#pragma unroll
    for (int off = 1; off < 8; off <<= 1) {
        m0 = fmaxf(m0, __shfl_xor_sync(0xffffffffu, m0, off));
        m1 = fmaxf(m1, __shfl_xor_sync(0xffffffffu, m1, off));
    }
    float e0 = __expf(s0 - m0), e1 = __expf(s1 - m1);
    float d0 = e0, d1 = e1;
#pragma unroll
    for (int off = 1; off < 8; off <<= 1) {
        d0 += __shfl_xor_sync(0xffffffffu, d0, off);
        d1 += __shfl_xor_sync(0xffffffffu, d1, off);
    }
    as_[w * 64 + lane]      = e0 / d0;   // position i*8+j == lane
    as_[w * 64 + 32 + lane] = e1 / d1;   // position i*8+j == 32+lane
    __syncwarp();

    // out[i][:] = sum_j attn[i][j] * v[j][:] ; lane owns 4 cols (float4)
    float4 o[8];
#pragma unroll
    for (int i = 0; i < 8; ++i) o[i] = make_float4(0.f, 0.f, 0.f, 0.f);
#pragma unroll
    for (int j = 0; j < 8; ++j) {
        float4 v4 = *(const float4*)(vs + (8 * b + j) * QP + h * D_DIM + lane * 4);
#pragma unroll
        for (int i = 0; i < 8; ++i) {
            float a = as_[w * 64 + i * 8 + j];
            o[i].x = fmaf(a, v4.x, o[i].x);
            o[i].y = fmaf(a, v4.y, o[i].y);
            o[i].z = fmaf(a, v4.z, o[i].z);
            o[i].w = fmaf(a, v4.w, o[i].w);
        }
    }
#pragma unroll
    for (int i = 0; i < 8; ++i) {
        size_t token = (size_t)blockIdx.x * TT + 8 * b + i;
        *(float4*)(out + token * E_DIM + h * D_DIM + lane * 4) = o[i];
    }
}

extern "C" void kernel_launch(void* const* d_in, const int* in_sizes, int n_in,
                              void* d_out, int out_size) {
    const float* x  = (const float*)d_in[0];
    const float* Wq = (const float*)d_in[1];
    const float* bq = (const float*)d_in[2];
    const float* Wk = (const float*)d_in[3];
    const float* bk = (const float*)d_in[4];
    const float* Wv = (const float*)d_in[5];
    const float* bv = (const float*)d_in[6];
    const float* P  = (const float*)d_in[7];
    float* out = (float*)d_out;

    const int tokens = in_sizes[0] / E_DIM;          // B*N = 65536
    const size_t smem = (size_t)(2 * TT * E_DIM + 3 * TT * QP + 8 * 64) * sizeof(float);

    cudaFuncSetAttribute(fused_kernel,
                         cudaFuncAttributeMaxDynamicSharedMemorySize, (int)smem);

    prep_kernel<<<E_DIM, E_DIM>>>(Wq, bq, Wk, bk, Wv, bv, P);
    fused_kernel<<<tokens / TT, 256, smem>>>(x, out);
}

// round 3
// speedup vs baseline: 3.2001x; 3.2001x over previous
#include <cuda_runtime.h>
#include <cstdint>

#define E_DIM 256
#define D_DIM 128
#define MT    128          // tokens per CTA
#define KCH   32           // K chunk

#define XS    36           // x chunk row stride (floats): bank = 4*row+col, conflict-free
#define WS    136          // w chunk row stride: 8*krow+ncol, conflict-free
#define QSTR  132          // q/k/v staging row stride

// smem layout (float offsets)
#define F_XS  0                    // 128*36   = 4608
#define F_WS  4608                 // 32*136   = 4352
#define F_QS  8960                 // 128*132  = 16896 (q, later v)
#define F_KS  25856                // 16896
#define F_PR  42752                // 16 blocks * 64 = 1024
#define F_BI  43776                // 3*128 = 384
#define SMEM_FLOATS 44160          // 176,640 bytes

__device__ float g_W[3 * E_DIM * E_DIM];   // [p][e][n]  (K-major rows), tf32-rounded
__device__ float g_b[3 * E_DIM];

__device__ __forceinline__ float tf32r(float x) {
    float r; asm("cvt.rna.tf32.f32 %0, %1;" : "=f"(r) : "f"(x)); return r;
}

#define MMA_TF32(c, a, b) \
    asm volatile("mma.sync.aligned.m16n8k8.row.col.f32.tf32.tf32.f32 " \
        "{%0,%1,%2,%3}, {%4,%5,%6,%7}, {%8,%9}, {%0,%1,%2,%3};" \
        : "+f"((c)[0]), "+f"((c)[1]), "+f"((c)[2]), "+f"((c)[3]) \
        : "r"((a)[0]), "r"((a)[1]), "r"((a)[2]), "r"((a)[3]), \
          "r"((b)[0]), "r"((b)[1]))

// Fold P into Wq/Wk; store K-major [e][n], tf32-rounded.
__global__ void prep_kernel(const float* __restrict__ Wq, const float* __restrict__ bq,
                            const float* __restrict__ Wk, const float* __restrict__ bk,
                            const float* __restrict__ Wv, const float* __restrict__ bv,
                            const float* __restrict__ P) {
    int e = blockIdx.x, j = threadIdx.x;        // e = input feat, j = output col
    int h = j >> 7, jm = j & 127;
    float aq = 0.f, ak = 0.f;
#pragma unroll 4
    for (int d = 0; d < D_DIM; ++d) {
        float p = P[d * D_DIM + jm];
        aq = fmaf(Wq[(h * D_DIM + d) * E_DIM + e], p, aq);
        ak = fmaf(Wk[(h * D_DIM + d) * E_DIM + e], p, ak);
    }
    g_W[0 * 65536 + e * E_DIM + j] = tf32r(aq);
    g_W[1 * 65536 + e * E_DIM + j] = tf32r(ak);
    g_W[2 * 65536 + e * E_DIM + j] = tf32r(Wv[j * E_DIM + e]);   // y = x @ Wv^T
    if (e == 0) {
        float bqe = 0.f, bke = 0.f;
        for (int d = 0; d < D_DIM; ++d) {
            float p = P[d * D_DIM + jm];
            bqe = fmaf(bq[h * D_DIM + d], p, bqe);
            bke = fmaf(bk[h * D_DIM + d], p, bke);
        }
        g_b[0 * E_DIM + j] = bqe;
        g_b[1 * E_DIM + j] = bke;
        g_b[2 * E_DIM + j] = bv[j];
    }
}

// CTA = 128 tokens x 1 head. q/k/v via mma.sync tf32, in-CTA block attention.
__global__ __launch_bounds__(256)
void fused_kernel(const float* __restrict__ x, float* __restrict__ out) {
    extern __shared__ float sm[];
    const int tid  = threadIdx.x;
    const int w    = tid >> 5, lane = tid & 31;
    const int wm   = w >> 2, wn = w & 3;          // warp grid 2x4 over [128,128]
    const int tile = blockIdx.x >> 1, head = blockIdx.x & 1;

    float* xs    = sm + F_XS;
    float* wsm   = sm + F_WS;
    float* sbias = sm + F_BI;

    // stage bias slices for this head
    for (int i = tid; i < 384; i += 256)
        sbias[i] = g_b[(i >> 7) * E_DIM + head * D_DIM + (i & 127)];
    __syncthreads();

    const float4* xg4 = (const float4*)(x + (size_t)tile * MT * E_DIM);

    for (int p = 0; p < 3; ++p) {
        const float* wsrc = g_W + p * 65536 + head * D_DIM;

        // accumulators, bias-initialized
        float acc[4][4][4];
#pragma unroll
        for (int mi = 0; mi < 4; ++mi)
#pragma unroll
            for (int ni = 0; ni < 4; ++ni) {
                int col = wn * 32 + ni * 8 + 2 * (lane & 3);
                float b0 = sbias[p * 128 + col], b1 = sbias[p * 128 + col + 1];
                acc[mi][ni][0] = b0; acc[mi][ni][1] = b1;
                acc[mi][ni][2] = b0; acc[mi][ni][3] = b1;
            }

        float4 xr[4], wr[4];
        // prefetch chunk 0
#pragma unroll
        for (int i = 0; i < 4; ++i) {
            int idx = tid + i * 256;                       // 1024 float4s
            int m = idx >> 3, q = idx & 7;
            xr[i] = xg4[m * 64 + q];
            int r = idx >> 5, qq = idx & 31;
            wr[i] = *(const float4*)(wsrc + r * E_DIM + qq * 4);
        }

        for (int c = 0; c < 8; ++c) {
            __syncthreads();        // prior chunk's compute done
            // store prefetched regs -> smem (x gets tf32 rounding)
#pragma unroll
            for (int i = 0; i < 4; ++i) {
                int idx = tid + i * 256;
                int m = idx >> 3, q = idx & 7;
                float4 v = xr[i];
                v.x = tf32r(v.x); v.y = tf32r(v.y); v.z = tf32r(v.z); v.w = tf32r(v.w);
                *(float4*)(xs + m * XS + q * 4) = v;
                int r = idx >> 5, qq = idx & 31;
                *(float4*)(wsm + r * WS + qq * 4) = wr[i];
            }
            __syncthreads();
            // prefetch next chunk (overlaps with mma below)
            if (c < 7) {
                int k0 = (c + 1) * KCH;
#pragma unroll
                for (int i = 0; i < 4; ++i) {
                    int idx = tid + i * 256;
                    int m = idx >> 3, q = idx & 7;
                    xr[i] = xg4[m * 64 + (k0 >> 2) + q];
                    int r = idx >> 5, qq = idx & 31;
                    wr[i] = *(const float4*)(wsrc + (k0 + r) * E_DIM + qq * 4);
                }
            }
            // compute: 4 k8 steps
#pragma unroll
            for (int k8 = 0; k8 < 4; ++k8) {
                uint32_t a[4][4], b[4][2];
#pragma unroll
                for (int mi = 0; mi < 4; ++mi) {
                    const float* base = xs + (wm * 64 + mi * 16 + (lane >> 2)) * XS
                                           + k8 * 8 + (lane & 3);
                    a[mi][0] = __float_as_uint(base[0]);
                    a[mi][1] = __float_as_uint(base[8 * XS]);
                    a[mi][2] = __float_as_uint(base[4]);
                    a[mi][3] = __float_as_uint(base[8 * XS + 4]);
                }
#pragma unroll
                for (int ni = 0; ni < 4; ++ni) {
                    const float* base = wsm + (k8 * 8 + (lane & 3)) * WS
                                            + wn * 32 + ni * 8 + (lane >> 2);
                    b[ni][0] = __float_as_uint(base[0]);
                    b[ni][1] = __float_as_uint(base[4 * WS]);
                }
#pragma unroll
                for (int mi = 0; mi < 4; ++mi)
#pragma unroll
                    for (int ni = 0; ni < 4; ++ni)
                        MMA_TF32(acc[mi][ni], a[mi], b[ni]);
            }
        }

        // epilogue: accums -> staging  (q -> F_QS, k -> F_KS, v -> F_QS)
        float* stg = sm + ((p == 1) ? F_KS : F_QS);
#pragma unroll
        for (int mi = 0; mi < 4; ++mi) {
            int row = wm * 64 + mi * 16 + (lane >> 2);
#pragma unroll
            for (int ni = 0; ni < 4; ++ni) {
                int col = wn * 32 + ni * 8 + 2 * (lane & 3);
                stg[row * QSTR + col]           = acc[mi][ni][0];
                stg[row * QSTR + col + 1]       = acc[mi][ni][1];
                stg[(row + 8) * QSTR + col]     = acc[mi][ni][2];
                stg[(row + 8) * QSTR + col + 1] = acc[mi][ni][3];
            }
        }

        if (p == 1) {
            // ---- scores + softmax: warp w handles blocks 2w, 2w+1 ----
            __syncthreads();
            float* qs = sm + F_QS; float* ks = sm + F_KS;
            const float scl = 0.08838834764831845f;   // 1/sqrt(128)
            for (int bb = 0; bb < 2; ++bb) {
                int blk = w * 2 + bb;
                int i0 = lane >> 3, j0 = lane & 7;
                const float4* q0 = (const float4*)(qs + (8 * blk + i0) * QSTR);
                const float4* q1 = (const float4*)(qs + (8 * blk + i0 + 4) * QSTR);
                const float4* k0 = (const float4*)(ks + (8 * blk + j0) * QSTR);
                float s0 = 0.f, s1 = 0.f;
#pragma unroll
                for (int t = 0; t < 32; ++t) {
                    float4 kk = k0[t];
                    float4 aa = q0[t];
                    s0 += aa.x * kk.x + aa.y * kk.y + aa.z * kk.z + aa.w * kk.w;
                    float4 cc = q1[t];
                    s1 += cc.x * kk.x + cc.y * kk.y + cc.z * kk.z + cc.w * kk.w;
                }
                s0 *= scl; s1 *= scl;
                float m0 = s0, m1 = s1;
#pragma unroll
                for (int off = 1; off < 8; off <<= 1) {
                    m0 = fmaxf(m0, __shfl_xor_sync(0xffffffffu, m0, off));
                    m1 = fmaxf(m1, __shfl_xor_sync(0xffffffffu, m1, off));
                }
                float e0 = __expf(s0 - m0), e1 = __expf(s1 - m1);
                float d0 = e0, d1 = e1;
#pragma unroll
                for (int off = 1; off < 8; off <<= 1) {
                    d0 += __shfl_xor_sync(0xffffffffu, d0, off);
                    d1 += __shfl_xor_sync(0xffffffffu, d1, off);
                }
                sm[F_PR + blk * 64 + lane]      = e0 / d0;
                sm[F_PR + blk * 64 + 32 + lane] = e1 / d1;
            }
        }
    }

    // ---- AV epilogue: v now in F_QS ----
    __syncthreads();
    float* vs = sm + F_QS;
    for (int bb = 0; bb < 2; ++bb) {
        int blk = w * 2 + bb;
        const float* prob = sm + F_PR + blk * 64;
        float4 o[8];
#pragma unroll
        for (int i = 0; i < 8; ++i) o[i] = make_float4(0.f, 0.f, 0.f, 0.f);
#pragma unroll
        for (int j = 0; j < 8; ++j) {
            float4 v4 = *(const float4*)(vs + (8 * blk + j) * QSTR + lane * 4);
#pragma unroll
            for (int i = 0; i < 8; ++i) {
                float a = prob[i * 8 + j];
                o[i].x = fmaf(a, v4.x, o[i].x);
                o[i].y = fmaf(a, v4.y, o[i].y);
                o[i].z = fmaf(a, v4.z, o[i].z);
                o[i].w = fmaf(a, v4.w, o[i].w);
            }
        }
#pragma unroll
        for (int i = 0; i < 8; ++i) {
            size_t token = (size_t)tile * MT + 8 * blk + i;
            *(float4*)(out + token * E_DIM + head * D_DIM + lane * 4) = o[i];
        }
    }
}

extern "C" void kernel_launch(void* const* d_in, const int* in_sizes, int n_in,
                              void* d_out, int out_size) {
    const float* x  = (const float*)d_in[0];
    const float* Wq = (const float*)d_in[1];
    const float* bq = (const float*)d_in[2];
    const float* Wk = (const float*)d_in[3];
    const float* bk = (const float*)d_in[4];
    const float* Wv = (const float*)d_in[5];
    const float* bv = (const float*)d_in[6];
    const float* P  = (const float*)d_in[7];
    float* out = (float*)d_out;

    const int tokens = in_sizes[0] / E_DIM;      // B*N
    const int tiles  = tokens / MT;
    const size_t smem = (size_t)SMEM_FLOATS * sizeof(float);   // 176,640 B

    cudaFuncSetAttribute(fused_kernel,
                         cudaFuncAttributeMaxDynamicSharedMemorySize, (int)smem);

    prep_kernel<<<E_DIM, E_DIM>>>(Wq, bq, Wk, bk, Wv, bv, P);
    fused_kernel<<<tiles * 2, 256, smem>>>(x, out);
}

// round 4
// speedup vs baseline: 4.6006x; 1.4377x over previous
#include <cuda_runtime.h>
#include <cstdint>

#define E_DIM 256
#define D_DIM 128
#define MT    64           // tokens per CTA
#define KCH   32           // K chunk

#define XS    36           // x chunk row stride (floats)
#define WS    136          // w chunk row stride
#define QSTR  132          // q/k/v staging row stride

// smem layout (float offsets)
#define F_XS  0                    // 64*36   = 2304
#define F_WS  2304                 // 32*136  = 4352
#define F_QS  6656                 // 64*132  = 8448 (q, later v)
#define F_KS  15104                // 8448
#define F_PR  23552                // 8 blocks * 64 = 512
#define F_BI  24064                // 384
#define SMEM_FLOATS 24448          // 97,792 bytes -> 2 CTAs/SM

__device__ float g_W[3 * E_DIM * E_DIM];   // [p][e][n]  K-major, tf32-rounded
__device__ float g_b[3 * E_DIM];

__device__ __forceinline__ float tf32r(float x) {
    float r; asm("cvt.rna.tf32.f32 %0, %1;" : "=f"(r) : "f"(x)); return r;
}

#define MMA_TF32(c, a, b) \
    asm volatile("mma.sync.aligned.m16n8k8.row.col.f32.tf32.tf32.f32 " \
        "{%0,%1,%2,%3}, {%4,%5,%6,%7}, {%8,%9}, {%0,%1,%2,%3};" \
        : "+f"((c)[0]), "+f"((c)[1]), "+f"((c)[2]), "+f"((c)[3]) \
        : "r"((a)[0]), "r"((a)[1]), "r"((a)[2]), "r"((a)[3]), \
          "r"((b)[0]), "r"((b)[1]))

// Fold P into Wq/Wk; store K-major [e][n], tf32-rounded.
__global__ void prep_kernel(const float* __restrict__ Wq, const float* __restrict__ bq,
                            const float* __restrict__ Wk, const float* __restrict__ bk,
                            const float* __restrict__ Wv, const float* __restrict__ bv,
                            const float* __restrict__ P) {
    int e = blockIdx.x, j = threadIdx.x;
    int h = j >> 7, jm = j & 127;
    float aq = 0.f, ak = 0.f;
#pragma unroll 4
    for (int d = 0; d < D_DIM; ++d) {
        float p = P[d * D_DIM + jm];
        aq = fmaf(Wq[(h * D_DIM + d) * E_DIM + e], p, aq);
        ak = fmaf(Wk[(h * D_DIM + d) * E_DIM + e], p, ak);
    }
    g_W[0 * 65536 + e * E_DIM + j] = tf32r(aq);
    g_W[1 * 65536 + e * E_DIM + j] = tf32r(ak);
    g_W[2 * 65536 + e * E_DIM + j] = tf32r(Wv[j * E_DIM + e]);
    if (e == 0) {
        float bqe = 0.f, bke = 0.f;
        for (int d = 0; d < D_DIM; ++d) {
            float p = P[d * D_DIM + jm];
            bqe = fmaf(bq[h * D_DIM + d], p, bqe);
            bke = fmaf(bk[h * D_DIM + d], p, bke);
        }
        g_b[0 * E_DIM + j] = bqe;
        g_b[1 * E_DIM + j] = bke;
        g_b[2 * E_DIM + j] = bv[j];
    }
}

// CTA = 64 tokens x 1 head. q/k/v via mma.sync tf32, in-CTA block attention.
__global__ __launch_bounds__(256, 2)
void fused_kernel(const float* __restrict__ x, float* __restrict__ out) {
    extern __shared__ float sm[];
    const int tid  = threadIdx.x;
    const int w    = tid >> 5, lane = tid & 31;
    const int wm   = w >> 2, wn = w & 3;          // warp grid 2x4 over [64,128]
    const int tile = blockIdx.x >> 1, head = blockIdx.x & 1;

    float* xs    = sm + F_XS;
    float* wsm   = sm + F_WS;
    float* sbias = sm + F_BI;

    for (int i = tid; i < 384; i += 256)
        sbias[i] = g_b[(i >> 7) * E_DIM + head * D_DIM + (i & 127)];
    __syncthreads();

    const float4* xg4 = (const float4*)(x + (size_t)tile * MT * E_DIM);

    for (int p = 0; p < 3; ++p) {
        const float* wsrc = g_W + p * 65536 + head * D_DIM;

        // accumulators, bias-initialized (warp tile 32x32: 2 m-tiles x 4 n-tiles)
        float acc[2][4][4];
#pragma unroll
        for (int mi = 0; mi < 2; ++mi)
#pragma unroll
            for (int ni = 0; ni < 4; ++ni) {
                int col = wn * 32 + ni * 8 + 2 * (lane & 3);
                float b0 = sbias[p * 128 + col], b1 = sbias[p * 128 + col + 1];
                acc[mi][ni][0] = b0; acc[mi][ni][1] = b1;
                acc[mi][ni][2] = b0; acc[mi][ni][3] = b1;
            }

        float4 xr[2], wr[4];
        // prefetch chunk 0
#pragma unroll
        for (int i = 0; i < 2; ++i) {
            int idx = tid + i * 256;                       // 512 float4s
            int m = idx >> 3, q = idx & 7;
            xr[i] = xg4[m * 64 + q];
        }
#pragma unroll
        for (int i = 0; i < 4; ++i) {
            int idx = tid + i * 256;                       // 1024 float4s
            int r = idx >> 5, qq = idx & 31;
            wr[i] = *(const float4*)(wsrc + r * E_DIM + qq * 4);
        }

        for (int c = 0; c < 8; ++c) {
            __syncthreads();
#pragma unroll
            for (int i = 0; i < 2; ++i) {
                int idx = tid + i * 256;
                int m = idx >> 3, q = idx & 7;
                float4 v = xr[i];
                v.x = tf32r(v.x); v.y = tf32r(v.y); v.z = tf32r(v.z); v.w = tf32r(v.w);
                *(float4*)(xs + m * XS + q * 4) = v;
            }
#pragma unroll
            for (int i = 0; i < 4; ++i) {
                int idx = tid + i * 256;
                int r = idx >> 5, qq = idx & 31;
                *(float4*)(wsm + r * WS + qq * 4) = wr[i];
            }
            __syncthreads();
            if (c < 7) {
                int k0 = (c + 1) * KCH;
#pragma unroll
                for (int i = 0; i < 2; ++i) {
                    int idx = tid + i * 256;
                    int m = idx >> 3, q = idx & 7;
                    xr[i] = xg4[m * 64 + (k0 >> 2) + q];
                }
#pragma unroll
                for (int i = 0; i < 4; ++i) {
                    int idx = tid + i * 256;
                    int r = idx >> 5, qq = idx & 31;
                    wr[i] = *(const float4*)(wsrc + (k0 + r) * E_DIM + qq * 4);
                }
            }
#pragma unroll
            for (int k8 = 0; k8 < 4; ++k8) {
                uint32_t a[2][4], b[4][2];
#pragma unroll
                for (int mi = 0; mi < 2; ++mi) {
                    const float* base = xs + (wm * 32 + mi * 16 + (lane >> 2)) * XS
                                           + k8 * 8 + (lane & 3);
                    a[mi][0] = __float_as_uint(base[0]);
                    a[mi][1] = __float_as_uint(base[8 * XS]);
                    a[mi][2] = __float_as_uint(base[4]);
                    a[mi][3] = __float_as_uint(base[8 * XS + 4]);
                }
#pragma unroll
                for (int ni = 0; ni < 4; ++ni) {
                    const float* base = wsm + (k8 * 8 + (lane & 3)) * WS
                                            + wn * 32 + ni * 8 + (lane >> 2);
                    b[ni][0] = __float_as_uint(base[0]);
                    b[ni][1] = __float_as_uint(base[4 * WS]);
                }
#pragma unroll
                for (int mi = 0; mi < 2; ++mi)
#pragma unroll
                    for (int ni = 0; ni < 4; ++ni)
                        MMA_TF32(acc[mi][ni], a[mi], b[ni]);
            }
        }

        // epilogue: accums -> staging (q -> F_QS, k -> F_KS, v -> F_QS)
        float* stg = sm + ((p == 1) ? F_KS : F_QS);
#pragma unroll
        for (int mi = 0; mi < 2; ++mi) {
            int row = wm * 32 + mi * 16 + (lane >> 2);
#pragma unroll
            for (int ni = 0; ni < 4; ++ni) {
                int col = wn * 32 + ni * 8 + 2 * (lane & 3);
                stg[row * QSTR + col]           = acc[mi][ni][0];
                stg[row * QSTR + col + 1]       = acc[mi][ni][1];
                stg[(row + 8) * QSTR + col]     = acc[mi][ni][2];
                stg[(row + 8) * QSTR + col + 1] = acc[mi][ni][3];
            }
        }

        if (p == 1) {
            // ---- scores + softmax: warp w handles block w (8 blocks) ----
            __syncthreads();
            float* qs = sm + F_QS; float* ks = sm + F_KS;
            const float scl = 0.08838834764831845f;   // 1/sqrt(128)
            int blk = w;
            int i0 = lane >> 3, j0 = lane & 7;
            const float4* q0 = (const float4*)(qs + (8 * blk + i0) * QSTR);
            const float4* q1 = (const float4*)(qs + (8 * blk + i0 + 4) * QSTR);
            const float4* k0 = (const float4*)(ks + (8 * blk + j0) * QSTR);
            float s0 = 0.f, s1 = 0.f;
#pragma unroll
            for (int t = 0; t < 32; ++t) {
                float4 kk = k0[t];
                float4 aa = q0[t];
                s0 += aa.x * kk.x + aa.y * kk.y + aa.z * kk.z + aa.w * kk.w;
                float4 cc = q1[t];
                s1 += cc.x * kk.x + cc.y * kk.y + cc.z * kk.z + cc.w * kk.w;
            }
            s0 *= scl; s1 *= scl;
            float m0 = s0, m1 = s1;
#pragma unroll
            for (int off = 1; off < 8; off <<= 1) {
                m0 = fmaxf(m0, __shfl_xor_sync(0xffffffffu, m0, off));
                m1 = fmaxf(m1, __shfl_xor_sync(0xffffffffu, m1, off));
            }
            float e0 = __expf(s0 - m0), e1 = __expf(s1 - m1);
            float d0 = e0, d1 = e1;
#pragma unroll
            for (int off = 1; off < 8; off <<= 1) {
                d0 += __shfl_xor_sync(0xffffffffu, d0, off);
                d1 += __shfl_xor_sync(0xffffffffu, d1, off);
            }
            sm[F_PR + blk * 64 + lane]      = e0 / d0;
            sm[F_PR + blk * 64 + 32 + lane] = e1 / d1;
        }
    }

    // ---- AV epilogue: v now in F_QS ----
    __syncthreads();
    float* vs = sm + F_QS;
    {
        int blk = w;
        const float* prob = sm + F_PR + blk * 64;
        float4 o[8];
#pragma unroll
        for (int i = 0; i < 8; ++i) o[i] = make_float4(0.f, 0.f, 0.f, 0.f);
#pragma unroll
        for (int j = 0; j < 8; ++j) {
            float4 v4 = *(const float4*)(vs + (8 * blk + j) * QSTR + lane * 4);
#pragma unroll
            for (int i = 0; i < 8; ++i) {
                float a = prob[i * 8 + j];
                o[i].x = fmaf(a, v4.x, o[i].x);
                o[i].y = fmaf(a, v4.y, o[i].y);
                o[i].z = fmaf(a, v4.z, o[i].z);
                o[i].w = fmaf(a, v4.w, o[i].w);
            }
        }
#pragma unroll
        for (int i = 0; i < 8; ++i) {
            size_t token = (size_t)tile * MT + 8 * blk + i;
            *(float4*)(out + token * E_DIM + head * D_DIM + lane * 4) = o[i];
        }
    }
}

extern "C" void kernel_launch(void* const* d_in, const int* in_sizes, int n_in,
                              void* d_out, int out_size) {
    const float* x  = (const float*)d_in[0];
    const float* Wq = (const float*)d_in[1];
    const float* bq = (const float*)d_in[2];
    const float* Wk = (const float*)d_in[3];
    const float* bk = (const float*)d_in[4];
    const float* Wv = (const float*)d_in[5];
    const float* bv = (const float*)d_in[6];
    const float* P  = (const float*)d_in[7];
    float* out = (float*)d_out;

    const int tokens = in_sizes[0] / E_DIM;      // B*N
    const int tiles  = tokens / MT;              // 1024
    const size_t smem = (size_t)SMEM_FLOATS * sizeof(float);   // 97,792 B

    cudaFuncSetAttribute(fused_kernel,
                         cudaFuncAttributeMaxDynamicSharedMemorySize, (int)smem);

    prep_kernel<<<E_DIM, E_DIM>>>(Wq, bq, Wk, bk, Wv, bv, P);
    fused_kernel<<<tiles * 2, 256, smem>>>(x, out);
}